// round 2
// baseline (speedup 1.0000x reference)
#include <cuda_runtime.h>
#include <math_constants.h>

#define BB 32
#define CC 64
#define HH 256
#define WW 256
#define HW (HH * WW)
#define TPB 256
#define HALF 8
#define INV_T 100.0f   // 1 / TEMPERATURE

__global__ __launch_bounds__(TPB)
void softargmax_kernel(const float* __restrict__ hm, float* __restrict__ out)
{
    const int bc = blockIdx.x;                 // 0 .. B*C-1
    const float* __restrict__ base = hm + (size_t)bc * HW;
    const int tid = threadIdx.x;

    // ---------------- Phase 1: argmax over 64K floats ----------------
    const float4* __restrict__ base4 = (const float4*)base;
    float best = -CUDART_INF_F;
    int bidx = 0;

    #pragma unroll 4
    for (int i = tid; i < HW / 4; i += TPB) {
        float4 v = base4[i];
        // strict > keeps the first occurrence within this thread's index set
        if (v.x > best) { best = v.x; bidx = 4 * i + 0; }
        if (v.y > best) { best = v.y; bidx = 4 * i + 1; }
        if (v.z > best) { best = v.z; bidx = 4 * i + 2; }
        if (v.w > best) { best = v.w; bidx = 4 * i + 3; }
    }

    __shared__ float sv[TPB];
    __shared__ int   si[TPB];
    sv[tid] = best;
    si[tid] = bidx;
    __syncthreads();

    // tree reduce with first-occurrence (min index) tie-break
    #pragma unroll
    for (int s = TPB / 2; s > 0; s >>= 1) {
        if (tid < s) {
            float ov = sv[tid + s];
            int   oi = si[tid + s];
            if (ov > sv[tid] || (ov == sv[tid] && oi < si[tid])) {
                sv[tid] = ov;
                si[tid] = oi;
            }
        }
        __syncthreads();
    }

    const float peak = sv[0];
    const int   idx  = si[0];
    const int   x0   = idx & (WW - 1);
    const int   y0   = idx >> 8;        // idx / WW

    // ---------------- Phase 2: windowed softmax moments ----------------
    const int xmin = max(x0 - HALF, 0);
    const int xmax = min(x0 + HALF, WW);
    const int ymin = max(y0 - HALF, 0);
    const int ymax = min(y0 + HALF, HH);

    const int wx = tid & 15;
    const int wy = tid >> 4;
    const int x = xmin + wx;
    const int y = ymin + wy;

    // moments centered at (x0, y0) to avoid catastrophic cancellation
    float e = 0.f, edx = 0.f, edy = 0.f, edxx = 0.f, edyy = 0.f, edxy = 0.f;
    if (x < xmax && y < ymax) {
        float v  = base[y * WW + x];
        e        = __expf((v - peak) * INV_T);
        float dx = (float)(x - x0);
        float dy = (float)(y - y0);
        edx  = e * dx;
        edy  = e * dy;
        edxx = e * dx * dx;
        edyy = e * dy * dy;
        edxy = e * dx * dy;
    }

    // warp reduce 6 values
    float vals[6] = { e, edx, edy, edxx, edyy, edxy };
    #pragma unroll
    for (int off = 16; off > 0; off >>= 1) {
        #pragma unroll
        for (int k = 0; k < 6; ++k)
            vals[k] += __shfl_down_sync(0xFFFFFFFFu, vals[k], off);
    }

    __shared__ float red[TPB / 32][6];
    const int warp = tid >> 5;
    const int lane = tid & 31;
    if (lane == 0) {
        #pragma unroll
        for (int k = 0; k < 6; ++k) red[warp][k] = vals[k];
    }
    __syncthreads();

    if (tid == 0) {
        float S = 0.f, Sdx = 0.f, Sdy = 0.f, Sdxx = 0.f, Sdyy = 0.f, Sdxy = 0.f;
        #pragma unroll
        for (int w = 0; w < TPB / 32; ++w) {
            S    += red[w][0];
            Sdx  += red[w][1];
            Sdy  += red[w][2];
            Sdxx += red[w][3];
            Sdyy += red[w][4];
            Sdxy += red[w][5];
        }
        float inv = 1.0f / S;
        float mdx = Sdx * inv;
        float mdy = Sdy * inv;
        float x_mean = (float)x0 + mdx;
        float y_mean = (float)y0 + mdy;
        float var_xx = Sdxx * inv - mdx * mdx;
        float var_yy = Sdyy * inv - mdy * mdy;
        float cov_xy = Sdxy * inv - mdx * mdy;

        // output layout: coords (B,C,2) | cov (B,C,2,2) | spread (B,C,1)
        out[bc * 2 + 0] = x_mean * (1.0f / (WW - 1));
        out[bc * 2 + 1] = y_mean * (1.0f / (HH - 1));

        float* covp = out + BB * CC * 2;
        covp[bc * 4 + 0] = var_xx;
        covp[bc * 4 + 1] = cov_xy;
        covp[bc * 4 + 2] = cov_xy;
        covp[bc * 4 + 3] = var_yy;

        out[BB * CC * 6 + bc] = var_xx + var_yy;
    }
}

extern "C" void kernel_launch(void* const* d_in, const int* in_sizes, int n_in,
                              void* d_out, int out_size)
{
    const float* hm = (const float*)d_in[0];
    float* out = (float*)d_out;
    softargmax_kernel<<<BB * CC, TPB>>>(hm, out);
}